// round 12
// baseline (speedup 1.0000x reference)
#include <cuda_runtime.h>
#include <cuda_fp16.h>
#include <stdint.h>

#define NN 262144
#define SCAN_BS 512
#define SCAN_NB 512   // NN / SCAN_BS

// ---------------- device scratch (static, no allocation) ----------------
__device__ int   g_deg[4 * NN];
__device__ int   g_ptr[4][NN + 1];
__device__ int   g_cnt[4][NN];
__device__ int   g_bsum[4][SCAN_NB];
__device__ int   g_src[4][4000000];     // gg needs 4M, others 2M
__device__ float g_wh[2000000];         // reordered hist edge weights
__device__ float g_wgg[4000000];        // per-edge dinv_gg[src] (gg graph, edge order)
__device__ float g_wss[2000000];        // per-edge dinv_ss[src] (ss graph, edge order)
__device__ float g_dinv_gg[NN], g_dinv_ss[NN];
__device__ float g_x8a[NN * 8], g_x8b[NN * 8], g_x8c[NN * 8];  // padded 5->8 dims
__device__ float g_gx[NN * 64];         // game_x (f32)
__device__ float g_s0[NN * 64];         // GraphConv output (f32, read by sage root term)
// fp16 feature chain (gather + GEMM operands; accumulation stays f32)
__device__ __half g_hgx[NN * 64];
__device__ __half g_h0[NN * 64], g_h1[NN * 64], g_h2[NN * 64];

// ---------------- packed f32x2 helpers (Blackwell FFMA2 via PTX) ----------------
typedef unsigned long long ull;
__device__ __forceinline__ ull pack2(float lo, float hi) {
    ull r; asm("mov.b64 %0, {%1, %2};" : "=l"(r) : "f"(lo), "f"(hi)); return r;
}
__device__ __forceinline__ void unpack2(ull v, float& lo, float& hi) {
    asm("mov.b64 {%0, %1}, %2;" : "=f"(lo), "=f"(hi) : "l"(v));
}
__device__ __forceinline__ ull ffma2(ull a, ull b, ull c) {
    ull d; asm("fma.rn.f32x2 %0, %1, %2, %3;" : "=l"(d) : "l"(a), "l"(b), "l"(c));
    return d;
}

// compile-time buffer picks
__device__ __forceinline__ const __half* pickh(int i) {
    switch (i) {
        case 0: return g_h0;
        case 1: return g_h1;
        case 2: return g_h2;
        default: return g_hgx;
    }
}
__device__ __forceinline__ __half* pickh_out(int i) {
    switch (i) {
        case 1: return g_h1;
        default: return g_h2;
    }
}
__device__ __forceinline__ const float* pick8(int i) {
    switch (i) {
        case 0: return g_x8a;
        case 1: return g_x8b;
        default: return g_x8c;
    }
}
__device__ __forceinline__ float* pick8w(int i) {
    switch (i) {
        case 1: return g_x8b;
        default: return g_x8c;
    }
}

// ---------------- dual-destination fp16 gather: 2 independent chains per warp ----------------
// lane covers cols (2*lane, 2*lane+1) via one LDG.32 (half2) per row; f32 accumulate.
// MODE 0: w = g_wh[edge]. MODE 1: unweighted. MODE 2: w = g_wss[edge] (sequential).
template <int MODE>
__device__ __forceinline__ void dual_gather_h(const __half* __restrict__ x, int gi,
                                              int d0, int d1, int col,
                                              float& a0, float& a1, float& b0, float& b1,
                                              int& rn0, int& rn1) {
    const int* __restrict__ src = g_src[gi];
    int p0 = g_ptr[gi][d0], n0 = g_ptr[gi][d0 + 1] - p0;
    int p1 = g_ptr[gi][d1], n1 = g_ptr[gi][d1 + 1] - p1;
    int n = (n0 > n1) ? n0 : n1;
    a0 = a1 = b0 = b1 = 0.f;
    for (int k = 0; k < n; k++) {
        if (k < n0) {
            int s = src[p0 + k];
            float w;
            if (MODE == 0)      w = g_wh[p0 + k];
            else if (MODE == 2) w = g_wss[p0 + k];
            else                w = 1.f;
            float2 v = __half22float2(*(const __half2*)(x + (size_t)s * 64 + col));
            a0 = fmaf(w, v.x, a0); a1 = fmaf(w, v.y, a1);
        }
        if (k < n1) {
            int s = src[p1 + k];
            float w;
            if (MODE == 0)      w = g_wh[p1 + k];
            else if (MODE == 2) w = g_wss[p1 + k];
            else                w = 1.f;
            float2 v = __half22float2(*(const __half2*)(x + (size_t)s * 64 + col));
            b0 = fmaf(w, v.x, b0); b1 = fmaf(w, v.y, b1);
        }
    }
    rn0 = n0; rn1 = n1;
}

// ---------------- CSR build (edges INT32), gridded ----------------
__global__ void k_zero_deg() {
    int i = blockIdx.x * blockDim.x + threadIdx.x;
    if (i < 4 * NN) g_deg[i] = 0;
}

__global__ void k_count_all(const int* __restrict__ e0, const int* __restrict__ e1,
                            const int* __restrict__ e2, const int* __restrict__ e3,
                            int E0, int E1, int E2, int E3) {
    int i = blockIdx.x * blockDim.x + threadIdx.x;
    int gi, j; const int* ei; int E;
    if (i < E0)                { gi = 0; j = i;                ei = e0; E = E0; }
    else if (i < E0 + E1)      { gi = 1; j = i - E0;           ei = e1; E = E1; }
    else if (i < E0 + E1 + E2) { gi = 2; j = i - E0 - E1;      ei = e2; E = E2; }
    else if (i < E0 + E1 + E2 + E3) { gi = 3; j = i - E0 - E1 - E2; ei = e3; E = E3; }
    else return;
    atomicAdd(&g_deg[gi * NN + ei[E + j]], 1);
}

__global__ void k_scan1() {
    __shared__ int s[SCAN_BS];
    int gi = blockIdx.y;
    int tid = threadIdx.x;
    int i = blockIdx.x * SCAN_BS + tid;
    int v = g_deg[gi * NN + i];
    s[tid] = v;
    __syncthreads();
    for (int off = 1; off < SCAN_BS; off <<= 1) {
        int t = (tid >= off) ? s[tid - off] : 0;
        __syncthreads();
        s[tid] += t;
        __syncthreads();
    }
    g_ptr[gi][i] = s[tid] - v;
    if (tid == SCAN_BS - 1) g_bsum[gi][blockIdx.x] = s[tid];
}

__global__ void k_scan2() {
    __shared__ int s[SCAN_NB];
    int gi = blockIdx.x;
    int tid = threadIdx.x;
    int v = g_bsum[gi][tid];
    s[tid] = v;
    __syncthreads();
    for (int off = 1; off < SCAN_NB; off <<= 1) {
        int t = (tid >= off) ? s[tid - off] : 0;
        __syncthreads();
        s[tid] += t;
        __syncthreads();
    }
    g_bsum[gi][tid] = s[tid] - v;
}

// scan3 + dinv fused (deg is at hand)
__global__ void k_scan3(int E0, int E1, int E2, int E3) {
    int gi = blockIdx.y;
    int tid = threadIdx.x;
    int i = blockIdx.x * SCAN_BS + tid;
    int v = g_ptr[gi][i] + g_bsum[gi][blockIdx.x];
    g_ptr[gi][i] = v;
    g_cnt[gi][i] = v;
    if (i == 0) g_ptr[gi][NN] = (gi == 0) ? E0 : (gi == 1) ? E1 : (gi == 2) ? E2 : E3;
    if (gi == 0) {
        int d = g_deg[i];
        g_dinv_gg[i] = (d > 0) ? rsqrtf((float)d) : 0.f;
    } else if (gi == 3) {
        int d = g_deg[3 * NN + i];
        g_dinv_ss[i] = (d > 0) ? rsqrtf((float)d) : 0.f;
    }
}

// fill; also materializes edge-ordered weights (dinv computed by scan3 already)
__global__ void k_fill_all(const int* __restrict__ e0, const int* __restrict__ e1,
                           const int* __restrict__ e2, const int* __restrict__ e3,
                           const float* __restrict__ ea,
                           int E0, int E1, int E2, int E3) {
    int i = blockIdx.x * blockDim.x + threadIdx.x;
    int gi, j; const int* ei; int E;
    if (i < E0)                { gi = 0; j = i;                ei = e0; E = E0; }
    else if (i < E0 + E1)      { gi = 1; j = i - E0;           ei = e1; E = E1; }
    else if (i < E0 + E1 + E2) { gi = 2; j = i - E0 - E1;      ei = e2; E = E2; }
    else if (i < E0 + E1 + E2 + E3) { gi = 3; j = i - E0 - E1 - E2; ei = e3; E = E3; }
    else return;
    int r = ei[j];
    int c = ei[E + j];
    int p = atomicAdd(&g_cnt[gi][c], 1);
    g_src[gi][p] = r;
    if (gi == 0) g_wgg[p] = g_dinv_gg[r];
    else if (gi == 1) g_wh[p] = ea[j];
    else if (gi == 3) g_wss[p] = g_dinv_ss[r];
}

// ---------------- TAG1 (5-dim, padded to 8) ----------------
__global__ void k_pad(const float* __restrict__ x) {
    int i = blockIdx.x * blockDim.x + threadIdx.x;
    if (i < NN) {
        const float* r = x + (size_t)i * 5;
        size_t o = (size_t)i * 8;
        *(float4*)(g_x8a + o)     = make_float4(r[0], r[1], r[2], r[3]);
        *(float4*)(g_x8a + o + 4) = make_float4(r[4], 0.f, 0.f, 0.f);
    }
}

// one normalized hop in 5-dim space (thread per dst); edge-ordered weights
__global__ void k_hop5(int in_i, int out_i) {
    const float* __restrict__ x8 = pick8(in_i);
    float* __restrict__ y8 = pick8w(out_i);
    int d = blockIdx.x * blockDim.x + threadIdx.x;
    if (d >= NN) return;
    int beg = g_ptr[0][d], end = g_ptr[0][d + 1];
    float a0 = 0, a1 = 0, a2 = 0, a3 = 0, a4 = 0;
    for (int e = beg; e < end; e++) {
        int s = g_src[0][e];
        float w = g_wgg[e];
        size_t o = (size_t)s * 8;
        float4 v = *(const float4*)(x8 + o);
        float v4 = x8[o + 4];
        a0 = fmaf(w, v.x, a0); a1 = fmaf(w, v.y, a1);
        a2 = fmaf(w, v.z, a2); a3 = fmaf(w, v.w, a3);
        a4 = fmaf(w, v4, a4);
    }
    float sd = g_dinv_gg[d];
    size_t o = (size_t)d * 8;
    *(float4*)(y8 + o)     = make_float4(a0 * sd, a1 * sd, a2 * sd, a3 * sd);
    *(float4*)(y8 + o + 4) = make_float4(a4 * sd, 0.f, 0.f, 0.f);
}

// gx = relu(x8a@W0 + x8b@W1 + x8c@W2 + b); writes f32 + half copies
__global__ void k_tag1(const float* __restrict__ W, const float* __restrict__ b) {
    __shared__ __align__(16) float sW[960];
    __shared__ __align__(16) float sb[64];
    __shared__ __align__(16) float sx[8][16];
    int tid = threadIdx.x;
    for (int i = tid; i < 960; i += 256) sW[i] = W[i];
    if (tid < 64) sb[tid] = b[tid];
    int ni = tid >> 5, tc = tid & 31;
    size_t node = (size_t)blockIdx.x * 8 + ni;
    if (tc < 5)       sx[ni][tc] = g_x8a[node * 8 + tc];
    else if (tc < 10) sx[ni][tc] = g_x8b[node * 8 + (tc - 5)];
    else if (tc < 15) sx[ni][tc] = g_x8c[node * 8 + (tc - 10)];
    __syncthreads();
    int c0 = 2 * tc;
    ull acc = pack2(sb[c0], sb[c0 + 1]);
#pragma unroll
    for (int k = 0; k < 3; k++)
#pragma unroll
        for (int i = 0; i < 5; i++) {
            float xv = sx[ni][k * 5 + i];
            ull w = *(const ull*)&sW[(k * 5 + i) * 64 + c0];
            acc = ffma2(pack2(xv, xv), w, acc);
        }
    float a0, a1; unpack2(acc, a0, a1);
    a0 = fmaxf(a0, 0.f); a1 = fmaxf(a1, 0.f);
    *(float2*)&g_gx[node * 64 + c0] = make_float2(a0, a1);
    *(__half2*)&g_hgx[node * 64 + c0] = __floats2half2_rn(a0, a1);
}

// ---------------- standalone 64-dim ss hop: 2 dsts per warp, fp16 in/out ----------------
__global__ void k_hop64ss(int in_i, int out_i) {
    const __half* __restrict__ x = pickh(in_i);
    __half* __restrict__ yh = pickh_out(out_i);
    int wptr = blockIdx.x * 8 + (threadIdx.x >> 5);
    if (wptr >= NN / 2) return;
    int lane = threadIdx.x & 31;
    int col = 2 * lane;
    int d0 = wptr * 2, d1 = d0 + 1;
    float a0, a1, b0, b1; int n0, n1;
    dual_gather_h<2>(x, 3, d0, d1, col, a0, a1, b0, b1, n0, n1);
    float sc0 = g_dinv_ss[d0], sc1 = g_dinv_ss[d1];
    *(__half2*)(yh + (size_t)d0 * 64 + col) = __floats2half2_rn(a0 * sc0, a1 * sc0);
    *(__half2*)(yh + (size_t)d1 * 64 + col) = __floats2half2_rn(b0 * sc1, b1 * sc1);
}

// ============ fused hop+combine kernels: 32 nodes/block, 8 warps ============

// s0 = relu( (weighted-sum_{hist} gx) @ w_rel + b_rel + x_state @ w_root )  [f32 out]
__global__ void k_gc(const float* __restrict__ xs, const float* __restrict__ wrel,
                     const float* __restrict__ brel, const float* __restrict__ wroot) {
    __shared__ __align__(16) float sW[4096];
    __shared__ __align__(16) float sWo[384];
    __shared__ __align__(16) float sb[64];
    __shared__ __align__(16) float sx[2048];
    __shared__ __align__(16) float sxs[192];
    int tid = threadIdx.x;
    for (int i = tid; i < 4096; i += 256) sW[i] = wrel[i];
    for (int i = tid; i < 384; i += 256) sWo[i] = wroot[i];
    for (int i = tid; i < 192; i += 256) sxs[i] = xs[(size_t)blockIdx.x * 192 + i];
    if (tid < 64) sb[tid] = brel[tid];
    int tc = tid & 31, g = tid >> 5;
    int col = 2 * tc;
    for (int mm = 0; mm < 4; mm += 2) {
        int node = blockIdx.x * 32 + g * 4 + mm;
        float a0, a1, b0, b1; int n0, n1;
        dual_gather_h<0>(g_hgx, 1, node, node + 1, col, a0, a1, b0, b1, n0, n1);
        *(float2*)&sx[(g * 4 + mm) * 64 + col]     = make_float2(a0, a1);
        *(float2*)&sx[(g * 4 + mm + 1) * 64 + col] = make_float2(b0, b1);
    }
    __syncthreads();
    int c0 = col;
    ull bias = pack2(sb[c0], sb[c0 + 1]);
    ull acc0 = bias, acc1 = bias, acc2 = bias, acc3 = bias;
    int nb = g * 4;
#pragma unroll 8
    for (int j = 0; j < 64; j++) {
        ull w = *(const ull*)&sW[j * 64 + c0];
        acc0 = ffma2(pack2(sx[(nb + 0) * 64 + j], sx[(nb + 0) * 64 + j]), w, acc0);
        acc1 = ffma2(pack2(sx[(nb + 1) * 64 + j], sx[(nb + 1) * 64 + j]), w, acc1);
        acc2 = ffma2(pack2(sx[(nb + 2) * 64 + j], sx[(nb + 2) * 64 + j]), w, acc2);
        acc3 = ffma2(pack2(sx[(nb + 3) * 64 + j], sx[(nb + 3) * 64 + j]), w, acc3);
    }
#pragma unroll
    for (int j = 0; j < 6; j++) {
        ull w = *(const ull*)&sWo[j * 64 + c0];
        acc0 = ffma2(pack2(sxs[(nb + 0) * 6 + j], sxs[(nb + 0) * 6 + j]), w, acc0);
        acc1 = ffma2(pack2(sxs[(nb + 1) * 6 + j], sxs[(nb + 1) * 6 + j]), w, acc1);
        acc2 = ffma2(pack2(sxs[(nb + 2) * 6 + j], sxs[(nb + 2) * 6 + j]), w, acc2);
        acc3 = ffma2(pack2(sxs[(nb + 3) * 6 + j], sxs[(nb + 3) * 6 + j]), w, acc3);
    }
    size_t nbase = (size_t)blockIdx.x * 32 + nb;
    ull accs[4] = { acc0, acc1, acc2, acc3 };
#pragma unroll
    for (int m = 0; m < 4; m++) {
        float a0, a1; unpack2(accs[m], a0, a1);
        *(float2*)&g_s0[(nbase + m) * 64 + c0] = make_float2(fmaxf(a0, 0.f), fmaxf(a1, 0.f));
    }
}

// s0' = relu( (mean_{in} gx) @ w_l + b_l + s0 @ w_r )   [writes h0 only]
__global__ void k_sage(const float* __restrict__ wl, const float* __restrict__ bl,
                       const float* __restrict__ wr) {
    __shared__ __align__(16) float sW[4096];
    __shared__ __align__(16) float sb[64];
    __shared__ __align__(16) float sm[2048];
    __shared__ __align__(16) float ss[2048];
    int tid = threadIdx.x;
    size_t base = (size_t)blockIdx.x * 2048;
    for (int i = tid; i < 2048; i += 256) ss[i] = g_s0[base + i];
    for (int i = tid; i < 4096; i += 256) sW[i] = wl[i];
    if (tid < 64) sb[tid] = bl[tid];
    int tc = tid & 31, g = tid >> 5;
    int col = 2 * tc;
    for (int mm = 0; mm < 4; mm += 2) {
        int node = blockIdx.x * 32 + g * 4 + mm;
        float a0, a1, b0, b1; int n0, n1;
        dual_gather_h<1>(g_hgx, 2, node, node + 1, col, a0, a1, b0, b1, n0, n1);
        float sc0 = (n0 > 0) ? 1.f / (float)n0 : 1.f;
        float sc1 = (n1 > 0) ? 1.f / (float)n1 : 1.f;
        *(float2*)&sm[(g * 4 + mm) * 64 + col]     = make_float2(a0 * sc0, a1 * sc0);
        *(float2*)&sm[(g * 4 + mm + 1) * 64 + col] = make_float2(b0 * sc1, b1 * sc1);
    }
    __syncthreads();
    int c0 = col;
    int nb = g * 4;
    ull bias = pack2(sb[c0], sb[c0 + 1]);
    ull acc0 = bias, acc1 = bias, acc2 = bias, acc3 = bias;
#pragma unroll 8
    for (int j = 0; j < 64; j++) {
        ull w = *(const ull*)&sW[j * 64 + c0];
        acc0 = ffma2(pack2(sm[(nb + 0) * 64 + j], sm[(nb + 0) * 64 + j]), w, acc0);
        acc1 = ffma2(pack2(sm[(nb + 1) * 64 + j], sm[(nb + 1) * 64 + j]), w, acc1);
        acc2 = ffma2(pack2(sm[(nb + 2) * 64 + j], sm[(nb + 2) * 64 + j]), w, acc2);
        acc3 = ffma2(pack2(sm[(nb + 3) * 64 + j], sm[(nb + 3) * 64 + j]), w, acc3);
    }
    __syncthreads();
    for (int i = tid; i < 4096; i += 256) sW[i] = wr[i];
    __syncthreads();
#pragma unroll 8
    for (int j = 0; j < 64; j++) {
        ull w = *(const ull*)&sW[j * 64 + c0];
        acc0 = ffma2(pack2(ss[(nb + 0) * 64 + j], ss[(nb + 0) * 64 + j]), w, acc0);
        acc1 = ffma2(pack2(ss[(nb + 1) * 64 + j], ss[(nb + 1) * 64 + j]), w, acc1);
        acc2 = ffma2(pack2(ss[(nb + 2) * 64 + j], ss[(nb + 2) * 64 + j]), w, acc2);
        acc3 = ffma2(pack2(ss[(nb + 3) * 64 + j], ss[(nb + 3) * 64 + j]), w, acc3);
    }
    size_t nbase = (size_t)blockIdx.x * 32 + nb;
    ull accs[4] = { acc0, acc1, acc2, acc3 };
#pragma unroll
    for (int m = 0; m < 4; m++) {
        float a0, a1; unpack2(accs[m], a0, a1);
        a0 = fmaxf(a0, 0.f); a1 = fmaxf(a1, 0.f);
        *(__half2*)&g_h0[(nbase + m) * 64 + c0] = __floats2half2_rn(a0, a1);
    }
}

// t = relu(h0@W0 + h1@W1 + h2@W2 + s3@W3 + b);  out = t@lin_w + lin_b
// s3 computed IN-KERNEL (dual fp16 gather of h2 over ss graph) into st.
__global__ void k_tag2(const float* __restrict__ W, const float* __restrict__ b,
                       const float* __restrict__ lw, const float* __restrict__ lb,
                       float* __restrict__ out) {
    __shared__ __align__(16) float sW[4096];
    __shared__ __align__(16) float sx[2048];
    __shared__ __align__(16) float st[2048];
    __shared__ __align__(16) float sLin[512];
    __shared__ __align__(16) float sb[64];
    __shared__ __align__(16) float slb[8];
    int tid = threadIdx.x;
    for (int i = tid; i < 512; i += 256) sLin[i] = lw[i];
    if (tid < 64) sb[tid] = b[tid];
    if (tid < 8) slb[tid] = lb[tid];
    int tc = tid & 31, g = tid >> 5;
    int col = 2 * tc;
    for (int mm = 0; mm < 4; mm += 2) {
        int node = blockIdx.x * 32 + g * 4 + mm;
        float a0, a1, b0v, b1v; int n0, n1;
        dual_gather_h<2>(g_h2, 3, node, node + 1, col, a0, a1, b0v, b1v, n0, n1);
        float sc0 = g_dinv_ss[node], sc1 = g_dinv_ss[node + 1];
        *(float2*)&st[(g * 4 + mm) * 64 + col]     = make_float2(a0 * sc0, a1 * sc0);
        *(float2*)&st[(g * 4 + mm + 1) * 64 + col] = make_float2(b0v * sc1, b1v * sc1);
    }
    int c0 = col;
    int nb = g * 4;
    size_t base = (size_t)blockIdx.x * 2048;   // element offset into NN*64 arrays
    ull bias = pack2(sb[c0], sb[c0 + 1]);
    ull acc0 = bias, acc1 = bias, acc2 = bias, acc3 = bias;
#pragma unroll
    for (int stage = 0; stage < 4; stage++) {
        __syncthreads();    // prior sW/sx use complete (st ready before stage 3)
        if (stage < 3) {
            const __half* Hk = (stage == 0) ? g_h0 : (stage == 1) ? g_h1 : g_h2;
            const __half2* src2 = (const __half2*)(Hk + base);
            for (int i = tid; i < 1024; i += 256) {
                float2 f = __half22float2(src2[i]);
                *(float2*)&sx[2 * i] = f;
            }
        }
        for (int i = tid; i < 4096; i += 256) sW[i] = W[stage * 4096 + i];
        __syncthreads();
        const float* xb = (stage < 3) ? sx : st;
#pragma unroll 8
        for (int j = 0; j < 64; j++) {
            ull w = *(const ull*)&sW[j * 64 + c0];
            acc0 = ffma2(pack2(xb[(nb + 0) * 64 + j], xb[(nb + 0) * 64 + j]), w, acc0);
            acc1 = ffma2(pack2(xb[(nb + 1) * 64 + j], xb[(nb + 1) * 64 + j]), w, acc1);
            acc2 = ffma2(pack2(xb[(nb + 2) * 64 + j], xb[(nb + 2) * 64 + j]), w, acc2);
            acc3 = ffma2(pack2(xb[(nb + 3) * 64 + j], xb[(nb + 3) * 64 + j]), w, acc3);
        }
    }
    __syncthreads();   // done reading st as stage-3 input
    ull accs[4] = { acc0, acc1, acc2, acc3 };
#pragma unroll
    for (int m = 0; m < 4; m++) {
        float a0, a1; unpack2(accs[m], a0, a1);
        st[(nb + m) * 64 + c0]     = fmaxf(a0, 0.f);
        st[(nb + m) * 64 + c0 + 1] = fmaxf(a1, 0.f);
    }
    __syncthreads();
    int n = tid >> 3, o = tid & 7;
    float acc = slb[o];
#pragma unroll 8
    for (int j = 0; j < 64; j++) acc = fmaf(st[n * 64 + j], sLin[j * 8 + o], acc);
    out[((size_t)blockIdx.x * 32 + n) * 8 + o] = acc;
}

// ---------------- host launch (kernel launches ONLY) ----------------
extern "C" void kernel_launch(void* const* d_in, const int* in_sizes, int n_in,
                              void* d_out, int out_size) {
    const float* x_game     = (const float*)d_in[0];
    const float* x_state    = (const float*)d_in[1];
    const int* e_gg         = (const int*)d_in[2];
    const int* e_hist       = (const int*)d_in[3];
    const int* e_in         = (const int*)d_in[4];
    const int* e_ss         = (const int*)d_in[5];
    const float* ea_hist    = (const float*)d_in[6];
    const float* tag1_w     = (const float*)d_in[7];
    const float* tag1_b     = (const float*)d_in[8];
    const float* tag2_w     = (const float*)d_in[9];
    const float* tag2_b     = (const float*)d_in[10];
    const float* gc_w_rel   = (const float*)d_in[11];
    const float* gc_b_rel   = (const float*)d_in[12];
    const float* gc_w_root  = (const float*)d_in[13];
    const float* sage_w_l   = (const float*)d_in[14];
    const float* sage_b_l   = (const float*)d_in[15];
    const float* sage_w_r   = (const float*)d_in[16];
    const float* lin_w      = (const float*)d_in[17];
    const float* lin_b      = (const float*)d_in[18];

    int E0 = in_sizes[2] / 2, E1 = in_sizes[3] / 2, E2 = in_sizes[4] / 2, E3 = in_sizes[5] / 2;
    long long Etot = (long long)E0 + E1 + E2 + E3;

    // ---- CSR build ----
    k_zero_deg<<<(4 * NN + 255) / 256, 256>>>();
    k_count_all<<<(int)((Etot + 255) / 256), 256>>>(e_gg, e_hist, e_in, e_ss, E0, E1, E2, E3);
    {
        dim3 grid1(SCAN_NB, 4);
        k_scan1<<<grid1, SCAN_BS>>>();
        k_scan2<<<4, SCAN_NB>>>();
        k_scan3<<<grid1, SCAN_BS>>>(E0, E1, E2, E3);
    }
    k_fill_all<<<(int)((Etot + 255) / 256), 256>>>(e_gg, e_hist, e_in, e_ss, ea_hist,
                                                   E0, E1, E2, E3);

    // ---- TAGConv1 (game graph, 5-dim propagation) ----
    k_pad<<<(NN + 255) / 256, 256>>>(x_game);
    k_hop5<<<(NN + 255) / 256, 256>>>(0, 1);   // x8a -> x8b
    k_hop5<<<(NN + 255) / 256, 256>>>(1, 2);   // x8b -> x8c
    k_tag1<<<NN / 8, 256>>>(tag1_w, tag1_b);

    // ---- GraphConv (hist) : fp16 gather fused into combine ----
    k_gc<<<NN / 32, 256>>>(x_state, gc_w_rel, gc_b_rel, gc_w_root);

    // ---- SAGEConv (in, mean) : fp16 gather fused into combine ----
    k_sage<<<NN / 32, 256>>>(sage_w_l, sage_b_l, sage_w_r);

    // ---- TAGConv2 (ss): two fp16 dual-warp hops, third fused into tag2 ----
    k_hop64ss<<<NN / 16, 256>>>(0, 1);         // h0 -> h1
    k_hop64ss<<<NN / 16, 256>>>(1, 2);         // h1 -> h2
    k_tag2<<<NN / 32, 256>>>(tag2_w, tag2_b, lin_w, lin_b, (float*)d_out);
}

// round 13
// speedup vs baseline: 1.0362x; 1.0362x over previous
#include <cuda_runtime.h>
#include <cuda_fp16.h>
#include <stdint.h>

#define NN 262144
#define SCAN_BS 512
#define SCAN_NB 512   // NN / SCAN_BS

// ---------------- device scratch (static, no allocation) ----------------
__device__ int   g_deg[4 * NN];
__device__ int   g_ptr[4][NN + 1];
__device__ int   g_cnt[4][NN];
__device__ int   g_bsum[4][SCAN_NB];
__device__ int   g_src[4][4000000];     // gg needs 4M, others 2M
__device__ float g_wh[2000000];         // reordered hist edge weights
__device__ float g_wgg[4000000];        // per-edge dinv_gg[src] (gg graph, edge order)
__device__ float g_wss[2000000];        // per-edge dinv_ss[src] (ss graph, edge order)
__device__ float g_dinv_gg[NN], g_dinv_ss[NN];
__device__ float g_x8a[NN * 8], g_x8b[NN * 8], g_x8c[NN * 8];  // padded 5->8 dims
// fp16 feature chain (gather + GEMM operands; accumulation stays f32)
__device__ __half g_hgx[NN * 64];
__device__ __half g_h0[NN * 64], g_h1[NN * 64], g_h2[NN * 64];

// ---------------- packed f32x2 helpers (Blackwell FFMA2 via PTX) ----------------
typedef unsigned long long ull;
__device__ __forceinline__ ull pack2(float lo, float hi) {
    ull r; asm("mov.b64 %0, {%1, %2};" : "=l"(r) : "f"(lo), "f"(hi)); return r;
}
__device__ __forceinline__ void unpack2(ull v, float& lo, float& hi) {
    asm("mov.b64 {%0, %1}, %2;" : "=f"(lo), "=f"(hi) : "l"(v));
}
__device__ __forceinline__ ull ffma2(ull a, ull b, ull c) {
    ull d; asm("fma.rn.f32x2 %0, %1, %2, %3;" : "=l"(d) : "l"(a), "l"(b), "l"(c));
    return d;
}

// compile-time buffer picks
__device__ __forceinline__ const __half* pickh(int i) {
    switch (i) {
        case 0: return g_h0;
        case 1: return g_h1;
        case 2: return g_h2;
        default: return g_hgx;
    }
}
__device__ __forceinline__ __half* pickh_out(int i) {
    switch (i) {
        case 1: return g_h1;
        default: return g_h2;
    }
}
__device__ __forceinline__ const float* pick8(int i) {
    switch (i) {
        case 0: return g_x8a;
        case 1: return g_x8b;
        default: return g_x8c;
    }
}
__device__ __forceinline__ float* pick8w(int i) {
    switch (i) {
        case 1: return g_x8b;
        default: return g_x8c;
    }
}

// ---------------- dual-destination fp16 gather: 2 independent chains per warp ----------------
// lane covers cols (2*lane, 2*lane+1) via one LDG.32 (half2) per row; f32 accumulate.
// MODE 0: w = g_wh[edge]. MODE 1: unweighted. MODE 2: w = g_wss[edge] (sequential).
template <int MODE>
__device__ __forceinline__ void dual_gather_h(const __half* __restrict__ x, int gi,
                                              int d0, int d1, int col,
                                              float& a0, float& a1, float& b0, float& b1,
                                              int& rn0, int& rn1) {
    const int* __restrict__ src = g_src[gi];
    int p0 = g_ptr[gi][d0], n0 = g_ptr[gi][d0 + 1] - p0;
    int p1 = g_ptr[gi][d1], n1 = g_ptr[gi][d1 + 1] - p1;
    int n = (n0 > n1) ? n0 : n1;
    a0 = a1 = b0 = b1 = 0.f;
    for (int k = 0; k < n; k++) {
        if (k < n0) {
            int s = src[p0 + k];
            float w;
            if (MODE == 0)      w = g_wh[p0 + k];
            else if (MODE == 2) w = g_wss[p0 + k];
            else                w = 1.f;
            float2 v = __half22float2(*(const __half2*)(x + (size_t)s * 64 + col));
            a0 = fmaf(w, v.x, a0); a1 = fmaf(w, v.y, a1);
        }
        if (k < n1) {
            int s = src[p1 + k];
            float w;
            if (MODE == 0)      w = g_wh[p1 + k];
            else if (MODE == 2) w = g_wss[p1 + k];
            else                w = 1.f;
            float2 v = __half22float2(*(const __half2*)(x + (size_t)s * 64 + col));
            b0 = fmaf(w, v.x, b0); b1 = fmaf(w, v.y, b1);
        }
    }
    rn0 = n0; rn1 = n1;
}

// ---------------- CSR build (edges INT32), gridded ----------------
__global__ void k_zero_deg() {
    int i = blockIdx.x * blockDim.x + threadIdx.x;
    if (i < 4 * NN) g_deg[i] = 0;
}

__global__ void k_count_all(const int* __restrict__ e0, const int* __restrict__ e1,
                            const int* __restrict__ e2, const int* __restrict__ e3,
                            int E0, int E1, int E2, int E3) {
    int i = blockIdx.x * blockDim.x + threadIdx.x;
    int gi, j; const int* ei; int E;
    if (i < E0)                { gi = 0; j = i;                ei = e0; E = E0; }
    else if (i < E0 + E1)      { gi = 1; j = i - E0;           ei = e1; E = E1; }
    else if (i < E0 + E1 + E2) { gi = 2; j = i - E0 - E1;      ei = e2; E = E2; }
    else if (i < E0 + E1 + E2 + E3) { gi = 3; j = i - E0 - E1 - E2; ei = e3; E = E3; }
    else return;
    atomicAdd(&g_deg[gi * NN + ei[E + j]], 1);
}

__global__ void k_scan1() {
    __shared__ int s[SCAN_BS];
    int gi = blockIdx.y;
    int tid = threadIdx.x;
    int i = blockIdx.x * SCAN_BS + tid;
    int v = g_deg[gi * NN + i];
    s[tid] = v;
    __syncthreads();
    for (int off = 1; off < SCAN_BS; off <<= 1) {
        int t = (tid >= off) ? s[tid - off] : 0;
        __syncthreads();
        s[tid] += t;
        __syncthreads();
    }
    g_ptr[gi][i] = s[tid] - v;
    if (tid == SCAN_BS - 1) g_bsum[gi][blockIdx.x] = s[tid];
}

__global__ void k_scan2() {
    __shared__ int s[SCAN_NB];
    int gi = blockIdx.x;
    int tid = threadIdx.x;
    int v = g_bsum[gi][tid];
    s[tid] = v;
    __syncthreads();
    for (int off = 1; off < SCAN_NB; off <<= 1) {
        int t = (tid >= off) ? s[tid - off] : 0;
        __syncthreads();
        s[tid] += t;
        __syncthreads();
    }
    g_bsum[gi][tid] = s[tid] - v;
}

// scan3 + dinv fused (deg is at hand)
__global__ void k_scan3(int E0, int E1, int E2, int E3) {
    int gi = blockIdx.y;
    int tid = threadIdx.x;
    int i = blockIdx.x * SCAN_BS + tid;
    int v = g_ptr[gi][i] + g_bsum[gi][blockIdx.x];
    g_ptr[gi][i] = v;
    g_cnt[gi][i] = v;
    if (i == 0) g_ptr[gi][NN] = (gi == 0) ? E0 : (gi == 1) ? E1 : (gi == 2) ? E2 : E3;
    if (gi == 0) {
        int d = g_deg[i];
        g_dinv_gg[i] = (d > 0) ? rsqrtf((float)d) : 0.f;
    } else if (gi == 3) {
        int d = g_deg[3 * NN + i];
        g_dinv_ss[i] = (d > 0) ? rsqrtf((float)d) : 0.f;
    }
}

// fill; also materializes edge-ordered weights (dinv computed by scan3 already)
__global__ void k_fill_all(const int* __restrict__ e0, const int* __restrict__ e1,
                           const int* __restrict__ e2, const int* __restrict__ e3,
                           const float* __restrict__ ea,
                           int E0, int E1, int E2, int E3) {
    int i = blockIdx.x * blockDim.x + threadIdx.x;
    int gi, j; const int* ei; int E;
    if (i < E0)                { gi = 0; j = i;                ei = e0; E = E0; }
    else if (i < E0 + E1)      { gi = 1; j = i - E0;           ei = e1; E = E1; }
    else if (i < E0 + E1 + E2) { gi = 2; j = i - E0 - E1;      ei = e2; E = E2; }
    else if (i < E0 + E1 + E2 + E3) { gi = 3; j = i - E0 - E1 - E2; ei = e3; E = E3; }
    else return;
    int r = ei[j];
    int c = ei[E + j];
    int p = atomicAdd(&g_cnt[gi][c], 1);
    g_src[gi][p] = r;
    if (gi == 0) g_wgg[p] = g_dinv_gg[r];
    else if (gi == 1) g_wh[p] = ea[j];
    else if (gi == 3) g_wss[p] = g_dinv_ss[r];
}

// ---------------- TAG1 (5-dim, padded to 8) ----------------
__global__ void k_pad(const float* __restrict__ x) {
    int i = blockIdx.x * blockDim.x + threadIdx.x;
    if (i < NN) {
        const float* r = x + (size_t)i * 5;
        size_t o = (size_t)i * 8;
        *(float4*)(g_x8a + o)     = make_float4(r[0], r[1], r[2], r[3]);
        *(float4*)(g_x8a + o + 4) = make_float4(r[4], 0.f, 0.f, 0.f);
    }
}

// one normalized hop in 5-dim space (thread per dst); edge-ordered weights
__global__ void k_hop5(int in_i, int out_i) {
    const float* __restrict__ x8 = pick8(in_i);
    float* __restrict__ y8 = pick8w(out_i);
    int d = blockIdx.x * blockDim.x + threadIdx.x;
    if (d >= NN) return;
    int beg = g_ptr[0][d], end = g_ptr[0][d + 1];
    float a0 = 0, a1 = 0, a2 = 0, a3 = 0, a4 = 0;
    for (int e = beg; e < end; e++) {
        int s = g_src[0][e];
        float w = g_wgg[e];
        size_t o = (size_t)s * 8;
        float4 v = *(const float4*)(x8 + o);
        float v4 = x8[o + 4];
        a0 = fmaf(w, v.x, a0); a1 = fmaf(w, v.y, a1);
        a2 = fmaf(w, v.z, a2); a3 = fmaf(w, v.w, a3);
        a4 = fmaf(w, v4, a4);
    }
    float sd = g_dinv_gg[d];
    size_t o = (size_t)d * 8;
    *(float4*)(y8 + o)     = make_float4(a0 * sd, a1 * sd, a2 * sd, a3 * sd);
    *(float4*)(y8 + o + 4) = make_float4(a4 * sd, 0.f, 0.f, 0.f);
}

// hgx = relu(x8a@W0 + x8b@W1 + x8c@W2 + b)   [fp16 out only — f32 copy was dead]
__global__ void k_tag1(const float* __restrict__ W, const float* __restrict__ b) {
    __shared__ __align__(16) float sW[960];
    __shared__ __align__(16) float sb[64];
    __shared__ __align__(16) float sx[8][16];
    int tid = threadIdx.x;
    for (int i = tid; i < 960; i += 256) sW[i] = W[i];
    if (tid < 64) sb[tid] = b[tid];
    int ni = tid >> 5, tc = tid & 31;
    size_t node = (size_t)blockIdx.x * 8 + ni;
    if (tc < 5)       sx[ni][tc] = g_x8a[node * 8 + tc];
    else if (tc < 10) sx[ni][tc] = g_x8b[node * 8 + (tc - 5)];
    else if (tc < 15) sx[ni][tc] = g_x8c[node * 8 + (tc - 10)];
    __syncthreads();
    int c0 = 2 * tc;
    ull acc = pack2(sb[c0], sb[c0 + 1]);
#pragma unroll
    for (int k = 0; k < 3; k++)
#pragma unroll
        for (int i = 0; i < 5; i++) {
            float xv = sx[ni][k * 5 + i];
            ull w = *(const ull*)&sW[(k * 5 + i) * 64 + c0];
            acc = ffma2(pack2(xv, xv), w, acc);
        }
    float a0, a1; unpack2(acc, a0, a1);
    *(__half2*)&g_hgx[node * 64 + c0] = __floats2half2_rn(fmaxf(a0, 0.f), fmaxf(a1, 0.f));
}

// ---------------- standalone 64-dim ss hop: 2 dsts per warp, fp16 in/out ----------------
__global__ void k_hop64ss(int in_i, int out_i) {
    const __half* __restrict__ x = pickh(in_i);
    __half* __restrict__ yh = pickh_out(out_i);
    int wptr = blockIdx.x * 8 + (threadIdx.x >> 5);
    if (wptr >= NN / 2) return;
    int lane = threadIdx.x & 31;
    int col = 2 * lane;
    int d0 = wptr * 2, d1 = d0 + 1;
    float a0, a1, b0, b1; int n0, n1;
    dual_gather_h<2>(x, 3, d0, d1, col, a0, a1, b0, b1, n0, n1);
    float sc0 = g_dinv_ss[d0], sc1 = g_dinv_ss[d1];
    *(__half2*)(yh + (size_t)d0 * 64 + col) = __floats2half2_rn(a0 * sc0, a1 * sc0);
    *(__half2*)(yh + (size_t)d1 * 64 + col) = __floats2half2_rn(b0 * sc1, b1 * sc1);
}

// ============ fused GraphConv + SAGE: 32 nodes/block, 8 warps ============
// s0 = relu( (w-sum_{hist} hgx) @ w_rel + b_rel + x_state @ w_root )  [stays in smem]
// h0 = relu( (mean_{in} hgx) @ w_l + b_l + s0 @ w_r )
__global__ void k_gcsage(const float* __restrict__ xs,
                         const float* __restrict__ wrel, const float* __restrict__ brel,
                         const float* __restrict__ wroot,
                         const float* __restrict__ wl, const float* __restrict__ bl,
                         const float* __restrict__ wr) {
    __shared__ __align__(16) float sW[4096];
    __shared__ __align__(16) float sWo[384];
    __shared__ __align__(16) float sb[64];
    __shared__ __align__(16) float sb2[64];
    __shared__ __align__(16) float sx[2048];   // hist aggregate
    __shared__ __align__(16) float sm[2048];   // in-graph mean aggregate
    __shared__ __align__(16) float ss[2048];   // s0 (GraphConv output)
    __shared__ __align__(16) float sxs[192];
    int tid = threadIdx.x;
    for (int i = tid; i < 4096; i += 256) sW[i] = wrel[i];
    for (int i = tid; i < 384; i += 256) sWo[i] = wroot[i];
    for (int i = tid; i < 192; i += 256) sxs[i] = xs[(size_t)blockIdx.x * 192 + i];
    if (tid < 64) { sb[tid] = brel[tid]; sb2[tid] = bl[tid]; }
    int tc = tid & 31, g = tid >> 5;
    int col = 2 * tc;
    // gather hist -> sx, in -> sm (warp-local rows)
    for (int mm = 0; mm < 4; mm += 2) {
        int node = blockIdx.x * 32 + g * 4 + mm;
        float a0, a1, b0, b1; int n0, n1;
        dual_gather_h<0>(g_hgx, 1, node, node + 1, col, a0, a1, b0, b1, n0, n1);
        *(float2*)&sx[(g * 4 + mm) * 64 + col]     = make_float2(a0, a1);
        *(float2*)&sx[(g * 4 + mm + 1) * 64 + col] = make_float2(b0, b1);
        dual_gather_h<1>(g_hgx, 2, node, node + 1, col, a0, a1, b0, b1, n0, n1);
        float sc0 = (n0 > 0) ? 1.f / (float)n0 : 1.f;
        float sc1 = (n1 > 0) ? 1.f / (float)n1 : 1.f;
        *(float2*)&sm[(g * 4 + mm) * 64 + col]     = make_float2(a0 * sc0, a1 * sc0);
        *(float2*)&sm[(g * 4 + mm + 1) * 64 + col] = make_float2(b0 * sc1, b1 * sc1);
    }
    __syncthreads();
    int c0 = col;
    int nb = g * 4;
    // ---- GEMM1: s0 = relu(sx@wrel + sxs@wroot + brel) -> ss ----
    {
        ull bias = pack2(sb[c0], sb[c0 + 1]);
        ull acc0 = bias, acc1 = bias, acc2 = bias, acc3 = bias;
#pragma unroll 8
        for (int j = 0; j < 64; j++) {
            ull w = *(const ull*)&sW[j * 64 + c0];
            acc0 = ffma2(pack2(sx[(nb + 0) * 64 + j], sx[(nb + 0) * 64 + j]), w, acc0);
            acc1 = ffma2(pack2(sx[(nb + 1) * 64 + j], sx[(nb + 1) * 64 + j]), w, acc1);
            acc2 = ffma2(pack2(sx[(nb + 2) * 64 + j], sx[(nb + 2) * 64 + j]), w, acc2);
            acc3 = ffma2(pack2(sx[(nb + 3) * 64 + j], sx[(nb + 3) * 64 + j]), w, acc3);
        }
#pragma unroll
        for (int j = 0; j < 6; j++) {
            ull w = *(const ull*)&sWo[j * 64 + c0];
            acc0 = ffma2(pack2(sxs[(nb + 0) * 6 + j], sxs[(nb + 0) * 6 + j]), w, acc0);
            acc1 = ffma2(pack2(sxs[(nb + 1) * 6 + j], sxs[(nb + 1) * 6 + j]), w, acc1);
            acc2 = ffma2(pack2(sxs[(nb + 2) * 6 + j], sxs[(nb + 2) * 6 + j]), w, acc2);
            acc3 = ffma2(pack2(sxs[(nb + 3) * 6 + j], sxs[(nb + 3) * 6 + j]), w, acc3);
        }
        ull accs[4] = { acc0, acc1, acc2, acc3 };
#pragma unroll
        for (int m = 0; m < 4; m++) {
            float a0, a1; unpack2(accs[m], a0, a1);
            ss[(nb + m) * 64 + c0]     = fmaxf(a0, 0.f);
            ss[(nb + m) * 64 + c0 + 1] = fmaxf(a1, 0.f);
        }
    }
    // ---- GEMM2: h0 = relu(sm@wl + ss@wr + bl) ----
    ull bias2 = pack2(sb2[c0], sb2[c0 + 1]);
    ull acc0 = bias2, acc1 = bias2, acc2 = bias2, acc3 = bias2;
    __syncthreads();   // all threads done with sW(wrel)
    for (int i = tid; i < 4096; i += 256) sW[i] = wl[i];
    __syncthreads();
#pragma unroll 8
    for (int j = 0; j < 64; j++) {
        ull w = *(const ull*)&sW[j * 64 + c0];
        acc0 = ffma2(pack2(sm[(nb + 0) * 64 + j], sm[(nb + 0) * 64 + j]), w, acc0);
        acc1 = ffma2(pack2(sm[(nb + 1) * 64 + j], sm[(nb + 1) * 64 + j]), w, acc1);
        acc2 = ffma2(pack2(sm[(nb + 2) * 64 + j], sm[(nb + 2) * 64 + j]), w, acc2);
        acc3 = ffma2(pack2(sm[(nb + 3) * 64 + j], sm[(nb + 3) * 64 + j]), w, acc3);
    }
    __syncthreads();
    for (int i = tid; i < 4096; i += 256) sW[i] = wr[i];
    __syncthreads();   // also guarantees ss fully written (was before first sync)
#pragma unroll 8
    for (int j = 0; j < 64; j++) {
        ull w = *(const ull*)&sW[j * 64 + c0];
        acc0 = ffma2(pack2(ss[(nb + 0) * 64 + j], ss[(nb + 0) * 64 + j]), w, acc0);
        acc1 = ffma2(pack2(ss[(nb + 1) * 64 + j], ss[(nb + 1) * 64 + j]), w, acc1);
        acc2 = ffma2(pack2(ss[(nb + 2) * 64 + j], ss[(nb + 2) * 64 + j]), w, acc2);
        acc3 = ffma2(pack2(ss[(nb + 3) * 64 + j], ss[(nb + 3) * 64 + j]), w, acc3);
    }
    size_t nbase = (size_t)blockIdx.x * 32 + nb;
    ull accs[4] = { acc0, acc1, acc2, acc3 };
#pragma unroll
    for (int m = 0; m < 4; m++) {
        float a0, a1; unpack2(accs[m], a0, a1);
        *(__half2*)&g_h0[(nbase + m) * 64 + c0] =
            __floats2half2_rn(fmaxf(a0, 0.f), fmaxf(a1, 0.f));
    }
}

// t = relu(h0@W0 + h1@W1 + h2@W2 + s3@W3 + b);  out = t@lin_w + lin_b
// s3 computed IN-KERNEL (dual fp16 gather of h2 over ss graph) into st.
__global__ void k_tag2(const float* __restrict__ W, const float* __restrict__ b,
                       const float* __restrict__ lw, const float* __restrict__ lb,
                       float* __restrict__ out) {
    __shared__ __align__(16) float sW[4096];
    __shared__ __align__(16) float sx[2048];
    __shared__ __align__(16) float st[2048];
    __shared__ __align__(16) float sLin[512];
    __shared__ __align__(16) float sb[64];
    __shared__ __align__(16) float slb[8];
    int tid = threadIdx.x;
    for (int i = tid; i < 512; i += 256) sLin[i] = lw[i];
    if (tid < 64) sb[tid] = b[tid];
    if (tid < 8) slb[tid] = lb[tid];
    int tc = tid & 31, g = tid >> 5;
    int col = 2 * tc;
    for (int mm = 0; mm < 4; mm += 2) {
        int node = blockIdx.x * 32 + g * 4 + mm;
        float a0, a1, b0v, b1v; int n0, n1;
        dual_gather_h<2>(g_h2, 3, node, node + 1, col, a0, a1, b0v, b1v, n0, n1);
        float sc0 = g_dinv_ss[node], sc1 = g_dinv_ss[node + 1];
        *(float2*)&st[(g * 4 + mm) * 64 + col]     = make_float2(a0 * sc0, a1 * sc0);
        *(float2*)&st[(g * 4 + mm + 1) * 64 + col] = make_float2(b0v * sc1, b1v * sc1);
    }
    int c0 = col;
    int nb = g * 4;
    size_t base = (size_t)blockIdx.x * 2048;   // element offset into NN*64 arrays
    ull bias = pack2(sb[c0], sb[c0 + 1]);
    ull acc0 = bias, acc1 = bias, acc2 = bias, acc3 = bias;
#pragma unroll
    for (int stage = 0; stage < 4; stage++) {
        __syncthreads();    // prior sW/sx use complete (st ready before stage 3)
        if (stage < 3) {
            const __half* Hk = (stage == 0) ? g_h0 : (stage == 1) ? g_h1 : g_h2;
            const __half2* src2 = (const __half2*)(Hk + base);
            for (int i = tid; i < 1024; i += 256) {
                float2 f = __half22float2(src2[i]);
                *(float2*)&sx[2 * i] = f;
            }
        }
        for (int i = tid; i < 4096; i += 256) sW[i] = W[stage * 4096 + i];
        __syncthreads();
        const float* xb = (stage < 3) ? sx : st;
#pragma unroll 8
        for (int j = 0; j < 64; j++) {
            ull w = *(const ull*)&sW[j * 64 + c0];
            acc0 = ffma2(pack2(xb[(nb + 0) * 64 + j], xb[(nb + 0) * 64 + j]), w, acc0);
            acc1 = ffma2(pack2(xb[(nb + 1) * 64 + j], xb[(nb + 1) * 64 + j]), w, acc1);
            acc2 = ffma2(pack2(xb[(nb + 2) * 64 + j], xb[(nb + 2) * 64 + j]), w, acc2);
            acc3 = ffma2(pack2(xb[(nb + 3) * 64 + j], xb[(nb + 3) * 64 + j]), w, acc3);
        }
    }
    __syncthreads();   // done reading st as stage-3 input
    ull accs[4] = { acc0, acc1, acc2, acc3 };
#pragma unroll
    for (int m = 0; m < 4; m++) {
        float a0, a1; unpack2(accs[m], a0, a1);
        st[(nb + m) * 64 + c0]     = fmaxf(a0, 0.f);
        st[(nb + m) * 64 + c0 + 1] = fmaxf(a1, 0.f);
    }
    __syncthreads();
    int n = tid >> 3, o = tid & 7;
    float acc = slb[o];
#pragma unroll 8
    for (int j = 0; j < 64; j++) acc = fmaf(st[n * 64 + j], sLin[j * 8 + o], acc);
    out[((size_t)blockIdx.x * 32 + n) * 8 + o] = acc;
}

// ---------------- host launch (kernel launches ONLY) ----------------
extern "C" void kernel_launch(void* const* d_in, const int* in_sizes, int n_in,
                              void* d_out, int out_size) {
    const float* x_game     = (const float*)d_in[0];
    const float* x_state    = (const float*)d_in[1];
    const int* e_gg         = (const int*)d_in[2];
    const int* e_hist       = (const int*)d_in[3];
    const int* e_in         = (const int*)d_in[4];
    const int* e_ss         = (const int*)d_in[5];
    const float* ea_hist    = (const float*)d_in[6];
    const float* tag1_w     = (const float*)d_in[7];
    const float* tag1_b     = (const float*)d_in[8];
    const float* tag2_w     = (const float*)d_in[9];
    const float* tag2_b     = (const float*)d_in[10];
    const float* gc_w_rel   = (const float*)d_in[11];
    const float* gc_b_rel   = (const float*)d_in[12];
    const float* gc_w_root  = (const float*)d_in[13];
    const float* sage_w_l   = (const float*)d_in[14];
    const float* sage_b_l   = (const float*)d_in[15];
    const float* sage_w_r   = (const float*)d_in[16];
    const float* lin_w      = (const float*)d_in[17];
    const float* lin_b      = (const float*)d_in[18];

    int E0 = in_sizes[2] / 2, E1 = in_sizes[3] / 2, E2 = in_sizes[4] / 2, E3 = in_sizes[5] / 2;
    long long Etot = (long long)E0 + E1 + E2 + E3;

    // ---- CSR build ----
    k_zero_deg<<<(4 * NN + 255) / 256, 256>>>();
    k_count_all<<<(int)((Etot + 255) / 256), 256>>>(e_gg, e_hist, e_in, e_ss, E0, E1, E2, E3);
    {
        dim3 grid1(SCAN_NB, 4);
        k_scan1<<<grid1, SCAN_BS>>>();
        k_scan2<<<4, SCAN_NB>>>();
        k_scan3<<<grid1, SCAN_BS>>>(E0, E1, E2, E3);
    }
    k_fill_all<<<(int)((Etot + 255) / 256), 256>>>(e_gg, e_hist, e_in, e_ss, ea_hist,
                                                   E0, E1, E2, E3);

    // ---- TAGConv1 (game graph, 5-dim propagation) ----
    k_pad<<<(NN + 255) / 256, 256>>>(x_game);
    k_hop5<<<(NN + 255) / 256, 256>>>(0, 1);   // x8a -> x8b
    k_hop5<<<(NN + 255) / 256, 256>>>(1, 2);   // x8b -> x8c
    k_tag1<<<NN / 8, 256>>>(tag1_w, tag1_b);

    // ---- GraphConv + SAGEConv fused (s0 never leaves shared memory) ----
    k_gcsage<<<NN / 32, 256>>>(x_state, gc_w_rel, gc_b_rel, gc_w_root,
                               sage_w_l, sage_b_l, sage_w_r);

    // ---- TAGConv2 (ss): two fp16 dual-warp hops, third fused into tag2 ----
    k_hop64ss<<<NN / 16, 256>>>(0, 1);         // h0 -> h1
    k_hop64ss<<<NN / 16, 256>>>(1, 2);         // h1 -> h2
    k_tag2<<<NN / 32, 256>>>(tag2_w, tag2_b, lin_w, lin_b, (float*)d_out);
}